// round 10
// baseline (speedup 1.0000x reference)
#include <cuda_runtime.h>
#include <cstdint>
#include <cstddef>

// ---------------- problem constants ----------------
#define BB 128
#define FF 512
#define TT 256
#define UU 1024

// ---------------- GEMM tiling ----------------
#define CTA_M 128
#define CTA_N 128
#define KC    32            // k per chunk (4 ksteps of 8)
#define NCHUNK (FF / KC)    // 16
#define NTHREADS 256        // 8 warps: 2(M) x 4(N), warp tile 64x32

#define FLAG_DELTA 4e-3f    // proven safe (rel_err 0.0 in R6/R9)
#define EXACT_BAND 5e-5
#define FLAG_CAP   (1u << 20)

// ---------------- scratch (device globals) ----------------
__device__ float g_a_perm[(size_t)64 * 64 * 32 * 4];   // W fragment-permuted fp32
__device__ float g_wt[(size_t)UU * FF];                // W^T  [U][F]
__device__ float g_xt[(size_t)BB * TT * FF];           // X^T  [B][T][F] (written by GEMM)
__device__ unsigned int g_flag_count;
__device__ unsigned int g_flag_list[FLAG_CAP];         // b[18:25)|u[8:18)|t[0:8)

// ---------------- helpers ----------------
__device__ __forceinline__ void cp16(uint32_t dst, const void* src) {
    asm volatile("cp.async.cg.shared.global [%0], [%1], 16;" :: "r"(dst), "l"(src));
}
__device__ __forceinline__ void cp_commit() { asm volatile("cp.async.commit_group;"); }
__device__ __forceinline__ void cp_wait1() { asm volatile("cp.async.wait_group 1;"); }
__device__ __forceinline__ void cp_wait0() { asm volatile("cp.async.wait_group 0;"); }

__device__ __forceinline__ void mma_tf32(float* c, const float4& a, const float2& b) {
    asm volatile(
        "mma.sync.aligned.m16n8k8.row.col.f32.tf32.tf32.f32 "
        "{%0,%1,%2,%3}, {%4,%5,%6,%7}, {%8,%9}, {%0,%1,%2,%3};"
        : "+f"(c[0]), "+f"(c[1]), "+f"(c[2]), "+f"(c[3])
        : "r"(__float_as_uint(a.x)), "r"(__float_as_uint(a.y)),
          "r"(__float_as_uint(a.z)), "r"(__float_as_uint(a.w)),
          "r"(__float_as_uint(b.x)), "r"(__float_as_uint(b.y)));
}

// ---------------- pre-pass: fragment-permute W (fp32) ----------------
__global__ __launch_bounds__(256)
void prep_w_kernel(const float* __restrict__ w) {
    const int idx = blockIdx.x * 256 + threadIdx.x;     // < 131072
    const int lane = idx & 31;
    const int mc   = (idx >> 5) & 63;
    const int kc   = idx >> 11;
    const int m = mc * 16 + (lane >> 2);
    const int k = kc * 8 + (lane & 3);
    float4 v;
    v.x = w[(size_t)k * UU + m];
    v.y = w[(size_t)k * UU + m + 8];
    v.z = w[(size_t)(k + 4) * UU + m];
    v.w = w[(size_t)(k + 4) * UU + m + 8];
    ((float4*)g_a_perm)[idx] = v;
    if (idx == 0) g_flag_count = 0;
}

__global__ __launch_bounds__(256)
void transpose_w_kernel(const float* __restrict__ w) {  // [F][U] -> [U][F]
    __shared__ float tile[32][33];
    const int u0 = blockIdx.x * 32, f0 = blockIdx.y * 32;
    const int tx = threadIdx.x, ty = threadIdx.y;       // 32 x 8
#pragma unroll
    for (int r = 0; r < 32; r += 8)
        tile[ty + r][tx] = w[(size_t)(f0 + ty + r) * UU + u0 + tx];
    __syncthreads();
#pragma unroll
    for (int r = 0; r < 32; r += 8)
        g_wt[(size_t)(u0 + ty + r) * FF + f0 + tx] = tile[tx][ty + r];
}

// ---------------- GEMM (unchanged from R9) ----------------
#define A_OFF      0
#define A_STAGE    16384
#define B_OFF      32768
#define B_STAGE    17408
#define B_ROWF     136
#define SMEM_TOTAL (32768 + 2 * B_STAGE)   // 67584

__global__ __launch_bounds__(NTHREADS, 2)
void snn_mma_gemm(const float* __restrict__ x, float* __restrict__ out) {
    extern __shared__ __align__(1024) char smem[];
    const uint32_t sb = (uint32_t)__cvta_generic_to_shared(smem);

    const int tid  = threadIdx.x;
    const int lane = tid & 31;
    const int wid  = tid >> 5;
    const int wm   = wid & 1;
    const int wn   = wid >> 1;
    const int nx   = blockIdx.x;
    const int mx   = blockIdx.y;
    const int b    = blockIdx.z;
    const int t0   = nx * CTA_N;
    const int mc0  = mx * 8;

    const float* xb = x + (size_t)b * FF * TT;

    auto issue = [&](int c, int s) {
        const uint32_t ast = sb + A_OFF + s * A_STAGE;
#pragma unroll
        for (int j = 0; j < 4; j++) {
            const int o = tid + j * 256;
            const int kt = o >> 8;
            const int off = o & 255;
            const size_t srcf = ((size_t)(c * 4 + kt) * 64 + mc0) * 128 + (size_t)off * 4;
            cp16(ast + o * 16, g_a_perm + srcf);
        }
        const uint32_t bst = sb + B_OFF + s * B_STAGE;
#pragma unroll
        for (int j = 0; j < 4; j++) {
            const int o = tid + j * 256;
            const int row = o >> 5;
            const int col = o & 31;
            cp16(bst + row * 544 + col * 16,
                 xb + ((size_t)(c * KC + row)) * TT + t0 + col * 4);
        }
        cp_commit();
    };

    float acc[4][4][4];
#pragma unroll
    for (int mt = 0; mt < 4; mt++)
#pragma unroll
        for (int nt = 0; nt < 4; nt++)
#pragma unroll
            for (int q = 0; q < 4; q++) acc[mt][nt][q] = 0.0f;

    issue(0, 0);
    issue(1, 1);

#pragma unroll 1
    for (int c = 0; c < NCHUNK; c++) {
        if (c == NCHUNK - 1) cp_wait0(); else cp_wait1();
        __syncthreads();

        const int s = c & 1;
        const float*  rawB = (const float*)(smem + B_OFF + s * B_STAGE);
        const float4* As   = (const float4*)(smem + A_OFF + s * A_STAGE);

        // fused X transpose: CTA mx == (c & 7) writes this tile to g_xt
        if (mx == (c & 7) && tid < CTA_N) {
            const int n = tid;
            float* orow = g_xt + ((size_t)b * TT + t0 + n) * FF + c * KC;
            float4 v;
#pragma unroll
            for (int kq = 0; kq < 8; kq++) {
                v.x = rawB[(kq * 4 + 0) * B_ROWF + n];
                v.y = rawB[(kq * 4 + 1) * B_ROWF + n];
                v.z = rawB[(kq * 4 + 2) * B_ROWF + n];
                v.w = rawB[(kq * 4 + 3) * B_ROWF + n];
                *(float4*)(orow + kq * 4) = v;
            }
        }

#pragma unroll
        for (int kt = 0; kt < 4; kt++) {
            float4 fa[4];
            float2 fb[4];
#pragma unroll
            for (int mt = 0; mt < 4; mt++)
                fa[mt] = As[(kt * 8 + wm * 4 + mt) * 32 + lane];
            const int kb = kt * 8 + (lane & 3);
            const int nb = lane >> 2;
#pragma unroll
            for (int nt = 0; nt < 4; nt++) {
                const int n = wn * 32 + nt * 8 + nb;
                fb[nt].x = rawB[kb * B_ROWF + n];
                fb[nt].y = rawB[(kb + 4) * B_ROWF + n];
            }
#pragma unroll
            for (int mt = 0; mt < 4; mt++)
#pragma unroll
                for (int nt = 0; nt < 4; nt++)
                    mma_tf32(acc[mt][nt], fa[mt], fb[nt]);
        }

        __syncthreads();
        if (c + 2 < NCHUNK) issue(c + 2, s);
    }

    const int m_base = mx * CTA_M + wm * 64 + (lane >> 2);
    const int t_base = t0 + wn * 32 + (lane & 3) * 2;
#pragma unroll
    for (int mt = 0; mt < 4; mt++) {
#pragma unroll
        for (int nt = 0; nt < 4; nt++) {
            const int m = m_base + mt * 16;
            const int t = t_base + nt * 8;
#pragma unroll
            for (int h = 0; h < 2; h++) {
                const int mm = m + h * 8;
                const float v0 = acc[mt][nt][h * 2 + 0];
                const float v1 = acc[mt][nt][h * 2 + 1];
                float2 r;
                r.x = v0 > 1.0f ? 1.0f : 0.0f;
                r.y = v1 > 1.0f ? 1.0f : 0.0f;
                *(float2*)(out + ((size_t)b * UU + mm) * TT + t) = r;
                if (fabsf(v0 - 1.0f) < FLAG_DELTA) {
                    unsigned idx = atomicAdd(&g_flag_count, 1u);
                    if (idx < FLAG_CAP)
                        g_flag_list[idx] = ((unsigned)b << 18) | ((unsigned)mm << 8) | (unsigned)t;
                }
                if (fabsf(v1 - 1.0f) < FLAG_DELTA) {
                    unsigned idx = atomicAdd(&g_flag_count, 1u);
                    if (idx < FLAG_CAP)
                        g_flag_list[idx] = ((unsigned)b << 18) | ((unsigned)mm << 8) | (unsigned)(t + 1);
                }
            }
        }
    }
}

// ---------------- two-tier fixup: 2 elements in flight per warp ----------------
#define FIX_WARPS 8
#define FIX_BLOCKS 1850

__device__ __forceinline__ void fix_exact(float* __restrict__ out,
                                          float (*ws)[FF], float (*xs)[FF],
                                          int wrp, int lane,
                                          const float4* wa, const float4* xa,
                                          int b, int u, int t) {
    // stage operands in f-order, replay exact sequential fp32 chain
#pragma unroll
    for (int j = 0; j < 4; j++) {
        const int f = 4 * (lane + j * 32);
        *(float4*)&ws[wrp][f] = wa[j];
        *(float4*)&xs[wrp][f] = xa[j];
    }
    __syncwarp();
    if (lane == 0) {
        float acc = 0.0f;
#pragma unroll 16
        for (int f = 0; f < FF; f++)
            acc = __fmaf_rn(ws[wrp][f], xs[wrp][f], acc);
        out[((size_t)b * UU + u) * TT + t] = acc > 1.0f ? 1.0f : 0.0f;
    }
    __syncwarp();
}

__global__ __launch_bounds__(FIX_WARPS * 32)
void fixup_kernel(float* __restrict__ out) {
    __shared__ float ws[FIX_WARPS][FF];
    __shared__ float xs[FIX_WARPS][FF];
    const unsigned n = min(g_flag_count, (unsigned)FLAG_CAP);
    const int lane = threadIdx.x & 31;
    const int wrp  = threadIdx.x >> 5;
    const unsigned gw = blockIdx.x * FIX_WARPS + wrp;
    const unsigned nw = gridDim.x * FIX_WARPS;

    for (unsigned i = gw; i < n; i += 2u * nw) {
        const unsigned j = i + nw;
        const bool has2 = (j < n);

        // --- decode both elements up front ---
        const unsigned code0 = g_flag_list[i];
        const unsigned code1 = has2 ? g_flag_list[j] : code0;
        const int b0 = code0 >> 18, u0 = (code0 >> 8) & 1023, t0 = code0 & 255;
        const int b1 = code1 >> 18, u1 = (code1 >> 8) & 1023, t1 = code1 & 255;

        const float4* wr0 = (const float4*)(g_wt + (size_t)u0 * FF);
        const float4* xr0 = (const float4*)(g_xt + ((size_t)b0 * TT + t0) * FF);
        const float4* wr1 = (const float4*)(g_wt + (size_t)u1 * FF);
        const float4* xr1 = (const float4*)(g_xt + ((size_t)b1 * TT + t1) * FF);

        // --- issue ALL loads for both elements (MLP x2) ---
        float4 wa0[4], xa0[4], wa1[4], xa1[4];
#pragma unroll
        for (int q = 0; q < 4; q++) {
            wa0[q] = wr0[lane + q * 32];
            xa0[q] = xr0[lane + q * 32];
            wa1[q] = wr1[lane + q * 32];
            xa1[q] = xr1[lane + q * 32];
        }

        // --- fp64 dots, interleaved ---
        double s0 = 0.0, s1 = 0.0;
#pragma unroll
        for (int q = 0; q < 4; q++) {
            s0 += (double)wa0[q].x * (double)xa0[q].x;
            s1 += (double)wa1[q].x * (double)xa1[q].x;
            s0 += (double)wa0[q].y * (double)xa0[q].y;
            s1 += (double)wa1[q].y * (double)xa1[q].y;
            s0 += (double)wa0[q].z * (double)xa0[q].z;
            s1 += (double)wa1[q].z * (double)xa1[q].z;
            s0 += (double)wa0[q].w * (double)xa0[q].w;
            s1 += (double)wa1[q].w * (double)xa1[q].w;
        }
#pragma unroll
        for (int o = 16; o > 0; o >>= 1) {     // deterministic tree-reduce, interleaved
            s0 += __shfl_xor_sync(0xFFFFFFFFu, s0, o);
            s1 += __shfl_xor_sync(0xFFFFFFFFu, s1, o);
        }

        // --- element 0 decision ---
        if (fabs(s0 - 1.0) > EXACT_BAND) {
            if (lane == 0)
                out[((size_t)b0 * UU + u0) * TT + t0] = (s0 > 1.0) ? 1.0f : 0.0f;
        } else {
            fix_exact(out, ws, xs, wrp, lane, wa0, xa0, b0, u0, t0);
        }
        // --- element 1 decision ---
        if (has2) {
            if (fabs(s1 - 1.0) > EXACT_BAND) {
                if (lane == 0)
                    out[((size_t)b1 * UU + u1) * TT + t1] = (s1 > 1.0) ? 1.0f : 0.0f;
            } else {
                fix_exact(out, ws, xs, wrp, lane, wa1, xa1, b1, u1, t1);
            }
        }
    }
}

// ---------------- host side ----------------
extern "C" void kernel_launch(void* const* d_in, const int* in_sizes, int n_in,
                              void* d_out, int out_size) {
    const float* x = (const float*)d_in[0];   // [B, F, T]
    const float* w = (const float*)d_in[1];   // [F, U]
    if (n_in >= 2 && in_sizes[0] == FF * UU && in_sizes[1] == BB * FF * TT) {
        const float* t = x; x = w; w = t;
    }
    float* out = (float*)d_out;

    prep_w_kernel<<<131072 / 256, 256>>>(w);
    transpose_w_kernel<<<dim3(UU / 32, FF / 32), dim3(32, 8)>>>(w);

    cudaFuncSetAttribute(snn_mma_gemm, cudaFuncAttributeMaxDynamicSharedMemorySize,
                         SMEM_TOTAL);
    snn_mma_gemm<<<dim3(TT / CTA_N, UU / CTA_M, BB), NTHREADS, SMEM_TOTAL>>>(x, out);

    fixup_kernel<<<FIX_BLOCKS, FIX_WARPS * 32>>>(out);
}